// round 2
// baseline (speedup 1.0000x reference)
#include <cuda_runtime.h>
#include <math.h>

// Problem-shape constants (fixed by the dataset)
#define NMAX 50000
#define EMAX 800000
#define EPMAX (EMAX + NMAX)

// ---------------- scratch (device globals; no allocation allowed) ----------
__device__ float g_xp[(size_t)NMAX * 256];     // x @ W            [N, 256]
__device__ float g_asrc[NMAX * 4];             // per-node src logits [N, H]
__device__ float g_adst[NMAX * 4];             // per-node dst logits [N, H]
__device__ float g_amax[NMAX * 4];             // segment max      [N, H]
__device__ float g_denom[NMAX * 4];            // segment sum      [N, H]
__device__ float g_edge[(size_t)EPMAX * 4];    // alpha, then ex   [E', H]
__device__ int   g_idx64;                      // 1 if edge_index is int64

// ---------------- helpers ---------------------------------------------------
__device__ __forceinline__ void atomicMaxFloat(float* addr, float v) {
    if (v >= 0.f) atomicMax((int*)addr, __float_as_int(v));
    else          atomicMin((unsigned int*)addr, __float_as_uint(v));
}

__device__ __forceinline__ void red_add_v4(float* p, float a, float b, float c, float d) {
    asm volatile("red.global.add.v4.f32 [%0], {%1,%2,%3,%4};"
                 :: "l"(p), "f"(a), "f"(b), "f"(c), "f"(d) : "memory");
}

// Decode edge index element i, robust to the harness storing int64 or int32.
__device__ __forceinline__ long long load_idx(const void* ei, long long i, int is64) {
    if (is64) return ((const long long*)ei)[i];
    return (long long)((const int*)ei)[i];
}

// ---------------- K-1: detect index width ----------------------------------
__global__ void detect_kernel(const unsigned int* __restrict__ ei32, int E) {
    if (threadIdx.x == 0 && blockIdx.x == 0) {
        unsigned int acc = 0;
        int n = E < 128 ? E : 128;
        for (int k = 0; k < n; k++) acc |= ei32[2 * k + 1];  // high words if int64
        g_idx64 = (acc == 0u) ? 1 : 0;
    }
}

// ---------------- K0: init out = bias, amax = -inf, denom = 0 --------------
__global__ void init_kernel(float* __restrict__ out, const float* __restrict__ bias, int N) {
    int i = blockIdx.x * blockDim.x + threadIdx.x;
    int total = N * 256;
    if (i < total) out[i] = bias[i & 255];
    if (i < N * 4) {
        g_amax[i]  = __int_as_float(0xff800000);  // -inf
        g_denom[i] = 0.f;
    }
}

// ---------------- K1: GEMM  xp[M,256] = x[M,128] @ W[128,256] ---------------
__global__ __launch_bounds__(256) void gemm_kernel(const float* __restrict__ A,
                                                   const float* __restrict__ B,
                                                   int M) {
    __shared__ float As[8][128];   // transposed: [k][row]
    __shared__ float Bs[8][128];   // [k][col]
    const int t = threadIdx.x;
    const int rowBase = blockIdx.x * 128;
    const int colBase = blockIdx.y * 128;
    const int tx = t & 15, ty = t >> 4;

    float acc[8][8];
#pragma unroll
    for (int i = 0; i < 8; i++)
#pragma unroll
        for (int j = 0; j < 8; j++) acc[i][j] = 0.f;

    const int arow = t >> 1, af4 = (t & 1) * 4;
    const int brow = t >> 5, bc4 = (t & 31) * 4;

    for (int kt = 0; kt < 128; kt += 8) {
        float4 av = make_float4(0.f, 0.f, 0.f, 0.f);
        if (rowBase + arow < M)
            av = *reinterpret_cast<const float4*>(&A[(size_t)(rowBase + arow) * 128 + kt + af4]);
        As[af4 + 0][arow] = av.x;
        As[af4 + 1][arow] = av.y;
        As[af4 + 2][arow] = av.z;
        As[af4 + 3][arow] = av.w;

        float4 bv = *reinterpret_cast<const float4*>(&B[(size_t)(kt + brow) * 256 + colBase + bc4]);
        *reinterpret_cast<float4*>(&Bs[brow][bc4]) = bv;
        __syncthreads();

#pragma unroll
        for (int kk = 0; kk < 8; kk++) {
            float a[8], b[8];
#pragma unroll
            for (int i = 0; i < 8; i++) a[i] = As[kk][ty * 8 + i];
#pragma unroll
            for (int j = 0; j < 8; j++) b[j] = Bs[kk][tx * 8 + j];
#pragma unroll
            for (int i = 0; i < 8; i++)
#pragma unroll
                for (int j = 0; j < 8; j++)
                    acc[i][j] = fmaf(a[i], b[j], acc[i][j]);
        }
        __syncthreads();
    }

#pragma unroll
    for (int i = 0; i < 8; i++) {
        int r = rowBase + ty * 8 + i;
        if (r < M) {
            float4 v0 = make_float4(acc[i][0], acc[i][1], acc[i][2], acc[i][3]);
            float4 v1 = make_float4(acc[i][4], acc[i][5], acc[i][6], acc[i][7]);
            *reinterpret_cast<float4*>(&g_xp[(size_t)r * 256 + colBase + tx * 8])     = v0;
            *reinterpret_cast<float4*>(&g_xp[(size_t)r * 256 + colBase + tx * 8 + 4]) = v1;
        }
    }
}

// ---------------- K2: a_src/a_dst dots (one warp per node) -------------------
__global__ void attn_dot_kernel(const float* __restrict__ att_src,
                                const float* __restrict__ att_dst, int N) {
    int warp = (blockIdx.x * blockDim.x + threadIdx.x) >> 5;
    int lane = threadIdx.x & 31;
    if (warp >= N) return;
    const float4* row = reinterpret_cast<const float4*>(g_xp + (size_t)warp * 256);
    float4 v1 = row[lane];
    float4 v2 = row[lane + 32];
    int h1 = lane >> 4;
    int h2 = 2 + h1;
    int c  = (lane * 4) & 63;

    float4 as1 = *reinterpret_cast<const float4*>(&att_src[h1 * 64 + c]);
    float4 ad1 = *reinterpret_cast<const float4*>(&att_dst[h1 * 64 + c]);
    float4 as2 = *reinterpret_cast<const float4*>(&att_src[h2 * 64 + c]);
    float4 ad2 = *reinterpret_cast<const float4*>(&att_dst[h2 * 64 + c]);

    float s1 = v1.x * as1.x + v1.y * as1.y + v1.z * as1.z + v1.w * as1.w;
    float t1 = v1.x * ad1.x + v1.y * ad1.y + v1.z * ad1.z + v1.w * ad1.w;
    float s2 = v2.x * as2.x + v2.y * as2.y + v2.z * as2.z + v2.w * as2.w;
    float t2 = v2.x * ad2.x + v2.y * ad2.y + v2.z * ad2.z + v2.w * ad2.w;

#pragma unroll
    for (int off = 8; off; off >>= 1) {
        s1 += __shfl_down_sync(0xffffffffu, s1, off, 16);
        t1 += __shfl_down_sync(0xffffffffu, t1, off, 16);
        s2 += __shfl_down_sync(0xffffffffu, s2, off, 16);
        t2 += __shfl_down_sync(0xffffffffu, t2, off, 16);
    }
    if ((lane & 15) == 0) {
        int h = lane >> 4;
        g_asrc[warp * 4 + h]     = s1;
        g_adst[warp * 4 + h]     = t1;
        g_asrc[warp * 4 + 2 + h] = s2;
        g_adst[warp * 4 + 2 + h] = t2;
    }
}

// ---------------- K3: alpha = leaky_relu(asrc[s]+adst[d]); segment max ------
__global__ void alpha_max_kernel(const void* __restrict__ ei, int E, int EP) {
    int i = blockIdx.x * blockDim.x + threadIdx.x;
    if (i >= EP * 4) return;
    int is64 = g_idx64;
    int e = i >> 2, h = i & 3;
    long long s, d;
    if (e < E) { s = load_idx(ei, e, is64); d = load_idx(ei, E + e, is64); }
    else       { s = d = e - E; }
    float a = g_asrc[s * 4 + h] + g_adst[d * 4 + h];
    a = a > 0.f ? a : 0.2f * a;
    g_edge[i] = a;
    atomicMaxFloat(&g_amax[d * 4 + h], a);
}

// ---------------- K4: ex = exp(alpha - amax[d]); segment sum -----------------
__global__ void exp_sum_kernel(const void* __restrict__ ei, int E, int EP) {
    int i = blockIdx.x * blockDim.x + threadIdx.x;
    if (i >= EP * 4) return;
    int is64 = g_idx64;
    int e = i >> 2, h = i & 3;
    long long d;
    if (e < E) d = load_idx(ei, E + e, is64);
    else       d = e - E;
    float ex = expf(g_edge[i] - g_amax[d * 4 + h]);
    g_edge[i] = ex;
    atomicAdd(&g_denom[d * 4 + h], ex);
}

// ---------------- K5: scatter messages (one warp per edge) -------------------
__global__ void scatter_kernel(const void* __restrict__ ei,
                               float* __restrict__ out, int E, int EP) {
    int warp = (blockIdx.x * blockDim.x + threadIdx.x) >> 5;
    int lane = threadIdx.x & 31;
    if (warp >= EP) return;
    int is64 = g_idx64;
    long long s, d;
    if (warp < E) { s = load_idx(ei, warp, is64); d = load_idx(ei, E + warp, is64); }
    else          { s = d = warp - E; }

    float c = 0.f;
    if (lane < 4) c = g_edge[(size_t)warp * 4 + lane] / g_denom[d * 4 + lane];
    float cA = __shfl_sync(0xffffffffu, c, lane >> 4);        // heads 0/1
    float cB = __shfl_sync(0xffffffffu, c, 2 + (lane >> 4));  // heads 2/3

    const float4* xrow = reinterpret_cast<const float4*>(g_xp + (size_t)s * 256);
    float4 vA = xrow[lane];
    float4 vB = xrow[lane + 32];

    float* o = out + (size_t)d * 256;
    red_add_v4(o + lane * 4,       vA.x * cA, vA.y * cA, vA.z * cA, vA.w * cA);
    red_add_v4(o + 128 + lane * 4, vB.x * cB, vB.y * cB, vB.z * cB, vB.w * cB);
}

// ---------------- launch -----------------------------------------------------
extern "C" void kernel_launch(void* const* d_in, const int* in_sizes, int n_in,
                              void* d_out, int out_size) {
    const float* x       = (const float*)d_in[0];
    const float* W       = (const float*)d_in[1];
    const float* att_src = (const float*)d_in[2];
    const float* att_dst = (const float*)d_in[3];
    const float* bias    = (const float*)d_in[4];
    const void*  ei      = d_in[5];
    float*       out     = (float*)d_out;

    const int N  = in_sizes[0] / 128;
    const int E  = in_sizes[5] / 2;
    const int EP = E + N;

    detect_kernel<<<1, 32>>>((const unsigned int*)ei, E);

    init_kernel<<<(N * 256 + 255) / 256, 256>>>(out, bias, N);

    dim3 ggrid((N + 127) / 128, 2);
    gemm_kernel<<<ggrid, 256>>>(x, W, N);

    attn_dot_kernel<<<(N * 32 + 255) / 256, 256>>>(att_src, att_dst, N);

    int epThreads = EP * 4;
    alpha_max_kernel<<<(epThreads + 255) / 256, 256>>>(ei, E, EP);
    exp_sum_kernel<<<(epThreads + 255) / 256, 256>>>(ei, E, EP);

    long long scatterThreads = (long long)EP * 32;
    scatter_kernel<<<(unsigned)((scatterThreads + 255) / 256), 256>>>(ei, out, E, EP);
}

// round 3
// speedup vs baseline: 1.3554x; 1.3554x over previous
#include <cuda_runtime.h>
#include <math.h>

#define NMAX 50000
#define EMAX 800000
#define EPMAX (EMAX + NMAX)

// ---------------- scratch (device globals) ----------------------------------
__device__ float g_xp[(size_t)NMAX * 256];   // x @ W  [N, 256]
__device__ float g_asrc[NMAX * 4];           // per-node src logits [N,H]
__device__ float g_adst[NMAX * 4];           // per-node dst logits [N,H]
__device__ int   g_cnt[NMAX];                // in-degree (incl self loop)
__device__ int   g_rowptr[NMAX + 1];         // CSR row pointers
__device__ int   g_cursor[NMAX];             // fill cursors
__device__ int   g_srcidx[EPMAX];            // CSR: src node per slot
__device__ float g_ex[(size_t)EPMAX * 4];    // exp(alpha) per slot [.,H]
__device__ int   g_idx64;                    // 1 if edge_index is int64

__device__ __forceinline__ long long load_idx(const void* ei, long long i, int is64) {
    if (is64) return ((const long long*)ei)[i];
    return (long long)((const int*)ei)[i];
}

// ---------------- detect index width (parallel) ------------------------------
__global__ void detect_kernel(const unsigned int* __restrict__ ei32, int E) {
    __shared__ int flag;
    if (threadIdx.x == 0) flag = 0;
    __syncthreads();
    int i = threadIdx.x;
    if (i < E && i < 128) {
        if (ei32[2 * i + 1] != 0u) atomicOr(&flag, 1);
    }
    __syncthreads();
    if (threadIdx.x == 0) g_idx64 = (flag == 0) ? 1 : 0;
}

// ---------------- init: degree = 1 (self loop) -------------------------------
__global__ void init_cnt_kernel(int N) {
    int i = blockIdx.x * blockDim.x + threadIdx.x;
    if (i < N) g_cnt[i] = 1;
}

// ---------------- GEMM  xp = x @ W  + fused attention dots -------------------
__global__ __launch_bounds__(256) void gemm_dots_kernel(const float* __restrict__ A,
                                                        const float* __restrict__ B,
                                                        const float* __restrict__ att_src,
                                                        const float* __restrict__ att_dst,
                                                        int M) {
    __shared__ float As[8][128];   // [k][row]
    __shared__ float Bs[8][128];   // [k][col]
    const int t = threadIdx.x;
    const int rowBase = blockIdx.x * 128;
    const int colBase = blockIdx.y * 128;
    const int tx = t & 15, ty = t >> 4;
    const int lane = t & 31;

    float acc[8][8];
#pragma unroll
    for (int i = 0; i < 8; i++)
#pragma unroll
        for (int j = 0; j < 8; j++) acc[i][j] = 0.f;

    const int arow = t >> 1, af4 = (t & 1) * 4;
    const int brow = t >> 5, bc4 = (t & 31) * 4;

    for (int kt = 0; kt < 128; kt += 8) {
        float4 av = make_float4(0.f, 0.f, 0.f, 0.f);
        if (rowBase + arow < M)
            av = *reinterpret_cast<const float4*>(&A[(size_t)(rowBase + arow) * 128 + kt + af4]);
        As[af4 + 0][arow] = av.x;
        As[af4 + 1][arow] = av.y;
        As[af4 + 2][arow] = av.z;
        As[af4 + 3][arow] = av.w;

        float4 bv = *reinterpret_cast<const float4*>(&B[(size_t)(kt + brow) * 256 + colBase + bc4]);
        *reinterpret_cast<float4*>(&Bs[brow][bc4]) = bv;
        __syncthreads();

#pragma unroll
        for (int kk = 0; kk < 8; kk++) {
            float a[8], b[8];
#pragma unroll
            for (int i = 0; i < 8; i++) a[i] = As[kk][ty * 8 + i];
#pragma unroll
            for (int j = 0; j < 8; j++) b[j] = Bs[kk][tx * 8 + j];
#pragma unroll
            for (int i = 0; i < 8; i++)
#pragma unroll
                for (int j = 0; j < 8; j++)
                    acc[i][j] = fmaf(a[i], b[j], acc[i][j]);
        }
        __syncthreads();
    }

    // store xp tile
#pragma unroll
    for (int i = 0; i < 8; i++) {
        int r = rowBase + ty * 8 + i;
        if (r < M) {
            float4 v0 = make_float4(acc[i][0], acc[i][1], acc[i][2], acc[i][3]);
            float4 v1 = make_float4(acc[i][4], acc[i][5], acc[i][6], acc[i][7]);
            *reinterpret_cast<float4*>(&g_xp[(size_t)r * 256 + colBase + tx * 8])     = v0;
            *reinterpret_cast<float4*>(&g_xp[(size_t)r * 256 + colBase + tx * 8 + 4]) = v1;
        }
    }

    // fused attention dots: this tile covers heads hbase, hbase+1 fully.
    const int hbase = colBase >> 6;                       // 0 or 2
    const int attOff = (hbase + (tx >> 3)) * 64 + (tx & 7) * 8;
    float4 sA0 = *reinterpret_cast<const float4*>(&att_src[attOff]);
    float4 sA1 = *reinterpret_cast<const float4*>(&att_src[attOff + 4]);
    float4 dA0 = *reinterpret_cast<const float4*>(&att_dst[attOff]);
    float4 dA1 = *reinterpret_cast<const float4*>(&att_dst[attOff + 4]);

#pragma unroll
    for (int i = 0; i < 8; i++) {
        float sv = acc[i][0] * sA0.x + acc[i][1] * sA0.y + acc[i][2] * sA0.z + acc[i][3] * sA0.w
                 + acc[i][4] * sA1.x + acc[i][5] * sA1.y + acc[i][6] * sA1.z + acc[i][7] * sA1.w;
        float tv = acc[i][0] * dA0.x + acc[i][1] * dA0.y + acc[i][2] * dA0.z + acc[i][3] * dA0.w
                 + acc[i][4] * dA1.x + acc[i][5] * dA1.y + acc[i][6] * dA1.z + acc[i][7] * dA1.w;
#pragma unroll
        for (int off = 4; off; off >>= 1) {
            sv += __shfl_down_sync(0xffffffffu, sv, off, 8);
            tv += __shfl_down_sync(0xffffffffu, tv, off, 8);
        }
        if ((lane & 7) == 0) {
            int r = rowBase + ty * 8 + i;
            if (r < M) {
                int h = hbase + ((lane >> 3) & 1);
                g_asrc[r * 4 + h] = sv;
                g_adst[r * 4 + h] = tv;
            }
        }
    }
}

// ---------------- histogram of destinations ----------------------------------
__global__ void hist_kernel(const void* __restrict__ ei, int E) {
    int i = blockIdx.x * blockDim.x + threadIdx.x;
    if (i >= E) return;
    int is64 = g_idx64;
    int d = (int)load_idx(ei, E + i, is64);
    atomicAdd(&g_cnt[d], 1);
}

// ---------------- exclusive scan (single block) -------------------------------
__global__ __launch_bounds__(1024) void scan_kernel(int N) {
    __shared__ int part[1024];
    const int t = threadIdx.x;
    const int C = (N + 1023) / 1024;
    const int begin = t * C;
    const int endi  = min(begin + C, N);

    int sum = 0;
    for (int i = begin; i < endi; i++) sum += g_cnt[i];
    part[t] = sum;
    __syncthreads();
    // inclusive Hillis-Steele scan
    for (int off = 1; off < 1024; off <<= 1) {
        int v = (t >= off) ? part[t - off] : 0;
        __syncthreads();
        part[t] += v;
        __syncthreads();
    }
    int run = (t == 0) ? 0 : part[t - 1];
    for (int i = begin; i < endi; i++) {
        g_rowptr[i] = run;
        g_cursor[i] = run;
        run += g_cnt[i];
    }
    if (t == 1023) g_rowptr[N] = part[1023];
}

// ---------------- fill CSR slots ----------------------------------------------
__global__ void fill_kernel(const void* __restrict__ ei, int E, int EP) {
    int i = blockIdx.x * blockDim.x + threadIdx.x;
    if (i >= EP) return;
    int is64 = g_idx64;
    int s, d;
    if (i < E) { s = (int)load_idx(ei, i, is64); d = (int)load_idx(ei, E + i, is64); }
    else       { s = d = i - E; }
    int pos = atomicAdd(&g_cursor[d], 1);
    g_srcidx[pos] = s;
}

// ---------------- aggregate: one warp per destination node --------------------
__global__ __launch_bounds__(256) void aggregate_kernel(const float* __restrict__ bias,
                                                        float* __restrict__ out, int N) {
    const int warp = (blockIdx.x * blockDim.x + threadIdx.x) >> 5;
    const int lane = threadIdx.x & 31;
    if (warp >= N) return;

    const int start = g_rowptr[warp];
    const int end   = g_rowptr[warp + 1];

    const float4* asrc4 = reinterpret_cast<const float4*>(g_asrc);
    float4 ad = reinterpret_cast<const float4*>(g_adst)[warp];

    // pass 1: ex = exp(leaky_relu(asrc[s] + adst[n])), local denom
    float4 den = make_float4(0.f, 0.f, 0.f, 0.f);
    for (int pos = start + lane; pos < end; pos += 32) {
        int s = g_srcidx[pos];
        float4 a = asrc4[s];
        a.x += ad.x; a.y += ad.y; a.z += ad.z; a.w += ad.w;
        a.x = a.x > 0.f ? a.x : 0.2f * a.x;
        a.y = a.y > 0.f ? a.y : 0.2f * a.y;
        a.z = a.z > 0.f ? a.z : 0.2f * a.z;
        a.w = a.w > 0.f ? a.w : 0.2f * a.w;
        float4 ex = make_float4(expf(a.x), expf(a.y), expf(a.z), expf(a.w));
        reinterpret_cast<float4*>(g_ex)[pos] = ex;
        den.x += ex.x; den.y += ex.y; den.z += ex.z; den.w += ex.w;
    }
#pragma unroll
    for (int off = 16; off; off >>= 1) {
        den.x += __shfl_xor_sync(0xffffffffu, den.x, off);
        den.y += __shfl_xor_sync(0xffffffffu, den.y, off);
        den.z += __shfl_xor_sync(0xffffffffu, den.z, off);
        den.w += __shfl_xor_sync(0xffffffffu, den.w, off);
    }
    float4 inv = make_float4(1.f / den.x, 1.f / den.y, 1.f / den.z, 1.f / den.w);
    // per-lane head selectors: channels [lane*4, +4) -> head lane>>4; +128 -> head 2+(lane>>4)
    float invA = (lane >> 4) ? inv.y : inv.x;
    float invB = (lane >> 4) ? inv.w : inv.z;

    float4 accA = make_float4(0.f, 0.f, 0.f, 0.f);
    float4 accB = make_float4(0.f, 0.f, 0.f, 0.f);

    // pass 2: whole warp cooperates on one edge's 1KB row at a time
    for (int pos = start; pos < end; pos++) {
        int s = g_srcidx[pos];                    // broadcast
        float4 ex = reinterpret_cast<const float4*>(g_ex)[pos];  // broadcast
        float cA = ((lane >> 4) ? ex.y : ex.x) * invA;
        float cB = ((lane >> 4) ? ex.w : ex.z) * invB;
        const float4* xrow = reinterpret_cast<const float4*>(g_xp + (size_t)s * 256);
        float4 vA = xrow[lane];
        float4 vB = xrow[lane + 32];
        accA.x = fmaf(vA.x, cA, accA.x); accA.y = fmaf(vA.y, cA, accA.y);
        accA.z = fmaf(vA.z, cA, accA.z); accA.w = fmaf(vA.w, cA, accA.w);
        accB.x = fmaf(vB.x, cB, accB.x); accB.y = fmaf(vB.y, cB, accB.y);
        accB.z = fmaf(vB.z, cB, accB.z); accB.w = fmaf(vB.w, cB, accB.w);
    }

    float4 bA = reinterpret_cast<const float4*>(bias)[lane];
    float4 bB = reinterpret_cast<const float4*>(bias)[lane + 32];
    accA.x += bA.x; accA.y += bA.y; accA.z += bA.z; accA.w += bA.w;
    accB.x += bB.x; accB.y += bB.y; accB.z += bB.z; accB.w += bB.w;

    float4* orow = reinterpret_cast<float4*>(out + (size_t)warp * 256);
    orow[lane]      = accA;
    orow[lane + 32] = accB;
}

// ---------------- launch -------------------------------------------------------
extern "C" void kernel_launch(void* const* d_in, const int* in_sizes, int n_in,
                              void* d_out, int out_size) {
    const float* x       = (const float*)d_in[0];
    const float* W       = (const float*)d_in[1];
    const float* att_src = (const float*)d_in[2];
    const float* att_dst = (const float*)d_in[3];
    const float* bias    = (const float*)d_in[4];
    const void*  ei      = d_in[5];
    float*       out     = (float*)d_out;

    const int N  = in_sizes[0] / 128;
    const int E  = in_sizes[5] / 2;
    const int EP = E + N;

    detect_kernel<<<1, 128>>>((const unsigned int*)ei, E);
    init_cnt_kernel<<<(N + 255) / 256, 256>>>(N);

    dim3 ggrid((N + 127) / 128, 2);
    gemm_dots_kernel<<<ggrid, 256>>>(x, W, att_src, att_dst, N);

    hist_kernel<<<(E + 255) / 256, 256>>>(ei, E);
    scan_kernel<<<1, 1024>>>(N);
    fill_kernel<<<(EP + 255) / 256, 256>>>(ei, E, EP);

    aggregate_kernel<<<(N * 32 + 255) / 256, 256>>>(bias, out, N);
}

// round 5
// speedup vs baseline: 1.4093x; 1.0397x over previous
#include <cuda_runtime.h>
#include <math.h>
#include <stdint.h>

#define NMAX 50000
#define EMAX 800000
#define EPMAX (EMAX + NMAX)

// ---------------- scratch (device globals) ----------------------------------
__device__ float g_xp[(size_t)NMAX * 256];   // x @ W  [N, 256]
__device__ float g_asrc[NMAX * 4];           // per-node src logits [N,H]
__device__ float g_adst[NMAX * 4];           // per-node dst logits [N,H]
__device__ int   g_cnt[NMAX];                // in-degree (incl self loop)
__device__ int   g_rowptr[NMAX + 1];         // CSR row pointers
__device__ int   g_cursor[NMAX];             // fill cursors
__device__ int   g_srcidx[EPMAX];            // CSR: src node per slot
__device__ float g_ex[(size_t)EPMAX * 4];    // exp(alpha) per slot [.,H]
__device__ int   g_idx64;                    // 1 if edge_index is int64

__device__ __forceinline__ long long load_idx(const void* ei, long long i, int is64) {
    if (is64) return ((const long long*)ei)[i];
    return (long long)((const int*)ei)[i];
}

__device__ __forceinline__ float to_tf32(float f) {
    uint32_t u;
    asm("cvt.rn.tf32.f32 %0, %1;" : "=r"(u) : "f"(f));
    return __uint_as_float(u);
}

// ---------------- detect + init (fused) --------------------------------------
__global__ void detect_init_kernel(const unsigned int* __restrict__ ei32, int E, int N) {
    int i = blockIdx.x * blockDim.x + threadIdx.x;
    if (i < N) g_cnt[i] = 1;
    if (blockIdx.x == 0) {
        unsigned int v = 0;
        if (threadIdx.x < 128 && threadIdx.x < E) v = ei32[2 * threadIdx.x + 1];
        unsigned int any = __ballot_sync(0xffffffffu, v != 0u);
        any = __shfl_sync(0xffffffffu, any, 0);
        __shared__ int flag;
        if (threadIdx.x == 0) flag = 0;
        __syncthreads();
        if ((threadIdx.x & 31) == 0 && any) atomicOr(&flag, 1);
        __syncthreads();
        if (threadIdx.x == 0) g_idx64 = (flag == 0) ? 1 : 0;
    }
}

// ---------------- tf32 mma.sync GEMM + fused attention dots ------------------
// CTA: 128 rows x 128 cols, 8 warps in 2x4. Warp tile 64x32. K=128 in one stage.
// smem floats: As 128x132, Bs 128x132 (pitch-132 kills fragment bank conflicts),
// atts/attd 256 each, att partials 128x4.
#define SM_AS   0
#define SM_BS   16896
#define SM_ATTS 33792
#define SM_ATTD 34048
#define SM_PART 34304
#define SM_FLOATS (34304 + 512)

__global__ __launch_bounds__(256) void gemm_mma_kernel(const float* __restrict__ x,
                                                       const float* __restrict__ W,
                                                       const float* __restrict__ att_src,
                                                       const float* __restrict__ att_dst,
                                                       int M) {
    extern __shared__ float sm[];
    float* As   = sm + SM_AS;
    float* Bs   = sm + SM_BS;
    float* atts = sm + SM_ATTS;
    float* attd = sm + SM_ATTD;
    float* part = sm + SM_PART;

    const int t = threadIdx.x;
    const int m0 = blockIdx.x * 128;
    const int colBase = blockIdx.y * 128;

    if (t < 128) {
        part[t * 4 + 0] = 0.f; part[t * 4 + 1] = 0.f;
        part[t * 4 + 2] = 0.f; part[t * 4 + 3] = 0.f;
    }
    atts[t] = att_src[t];
    attd[t] = att_dst[t];

    // load A tile (128x128), tf32-rounded
    for (int i = t; i < 128 * 32; i += 256) {
        int row = i >> 5, c4 = (i & 31) * 4;
        float4 v = make_float4(0.f, 0.f, 0.f, 0.f);
        if (m0 + row < M)
            v = *reinterpret_cast<const float4*>(&x[(size_t)(m0 + row) * 128 + c4]);
        v.x = to_tf32(v.x); v.y = to_tf32(v.y); v.z = to_tf32(v.z); v.w = to_tf32(v.w);
        *reinterpret_cast<float4*>(&As[row * 132 + c4]) = v;  // 132*4B=528 is 16B-aligned
    }
    // load B tile: Bs[k][n] = W[k][colBase+n], tf32-rounded
    for (int i = t; i < 128 * 32; i += 256) {
        int row = i >> 5, c4 = (i & 31) * 4;
        float4 v = *reinterpret_cast<const float4*>(&W[(size_t)row * 256 + colBase + c4]);
        v.x = to_tf32(v.x); v.y = to_tf32(v.y); v.z = to_tf32(v.z); v.w = to_tf32(v.w);
        *reinterpret_cast<float4*>(&Bs[row * 132 + c4]) = v;
    }
    __syncthreads();

    const int wid = t >> 5, lane = t & 31;
    const int wr = wid >> 2;       // warp row: 0..1  (64 rows each)
    const int wc = wid & 3;        // warp col: 0..3  (32 cols each)
    const int grp = lane >> 2, t4 = lane & 3;

    float acc[4][4][4];
#pragma unroll
    for (int a = 0; a < 4; a++)
#pragma unroll
        for (int b = 0; b < 4; b++)
#pragma unroll
            for (int c = 0; c < 4; c++) acc[a][b][c] = 0.f;

#pragma unroll
    for (int ks = 0; ks < 16; ks++) {
        const int k0 = ks * 8;
        uint32_t af[4][4];
#pragma unroll
        for (int mf = 0; mf < 4; mf++) {
            const int r = wr * 64 + mf * 16 + grp;
            af[mf][0] = __float_as_uint(As[r * 132 + k0 + t4]);
            af[mf][1] = __float_as_uint(As[(r + 8) * 132 + k0 + t4]);
            af[mf][2] = __float_as_uint(As[r * 132 + k0 + 4 + t4]);
            af[mf][3] = __float_as_uint(As[(r + 8) * 132 + k0 + 4 + t4]);
        }
        uint32_t bf[4][2];
#pragma unroll
        for (int nf = 0; nf < 4; nf++) {
            const int c = wc * 32 + nf * 8 + grp;
            bf[nf][0] = __float_as_uint(Bs[(k0 + t4) * 132 + c]);
            bf[nf][1] = __float_as_uint(Bs[(k0 + 4 + t4) * 132 + c]);
        }
#pragma unroll
        for (int mf = 0; mf < 4; mf++)
#pragma unroll
            for (int nf = 0; nf < 4; nf++) {
                asm volatile(
                    "mma.sync.aligned.m16n8k8.row.col.f32.tf32.tf32.f32 "
                    "{%0,%1,%2,%3}, {%4,%5,%6,%7}, {%8,%9}, {%0,%1,%2,%3};"
                    : "+f"(acc[mf][nf][0]), "+f"(acc[mf][nf][1]),
                      "+f"(acc[mf][nf][2]), "+f"(acc[mf][nf][3])
                    : "r"(af[mf][0]), "r"(af[mf][1]), "r"(af[mf][2]), "r"(af[mf][3]),
                      "r"(bf[nf][0]), "r"(bf[nf][1]));
            }
    }

    // epilogue: store xp + fused attention dots
    const int head_loc = wc >> 1;                  // 0 or 1 within this col tile
#pragma unroll
    for (int mf = 0; mf < 4; mf++) {
        const int lrow_lo = wr * 64 + mf * 16 + grp;
        const int lrow_hi = lrow_lo + 8;
        const int grow_lo = m0 + lrow_lo;
        const int grow_hi = m0 + lrow_hi;

        float s_lo = 0.f, v_lo = 0.f, s_hi = 0.f, v_hi = 0.f;
#pragma unroll
        for (int nf = 0; nf < 4; nf++) {
            const int col = colBase + wc * 32 + nf * 8 + t4 * 2;
            const float a0 = atts[col], a1 = atts[col + 1];
            const float d0 = attd[col], d1 = attd[col + 1];
            s_lo = fmaf(acc[mf][nf][0], a0, fmaf(acc[mf][nf][1], a1, s_lo));
            v_lo = fmaf(acc[mf][nf][0], d0, fmaf(acc[mf][nf][1], d1, v_lo));
            s_hi = fmaf(acc[mf][nf][2], a0, fmaf(acc[mf][nf][3], a1, s_hi));
            v_hi = fmaf(acc[mf][nf][2], d0, fmaf(acc[mf][nf][3], d1, v_hi));
            if (grow_lo < M)
                *reinterpret_cast<float2*>(&g_xp[(size_t)grow_lo * 256 + col]) =
                    make_float2(acc[mf][nf][0], acc[mf][nf][1]);
            if (grow_hi < M)
                *reinterpret_cast<float2*>(&g_xp[(size_t)grow_hi * 256 + col]) =
                    make_float2(acc[mf][nf][2], acc[mf][nf][3]);
        }
        // reduce over the 4 lanes of the group (cols within warp tile)
#pragma unroll
        for (int off = 1; off < 4; off <<= 1) {
            s_lo += __shfl_xor_sync(0xffffffffu, s_lo, off);
            v_lo += __shfl_xor_sync(0xffffffffu, v_lo, off);
            s_hi += __shfl_xor_sync(0xffffffffu, s_hi, off);
            v_hi += __shfl_xor_sync(0xffffffffu, v_hi, off);
        }
        if (t4 == 0) {
            atomicAdd(&part[lrow_lo * 4 + head_loc * 2 + 0], s_lo);
            atomicAdd(&part[lrow_lo * 4 + head_loc * 2 + 1], v_lo);
            atomicAdd(&part[lrow_hi * 4 + head_loc * 2 + 0], s_hi);
            atomicAdd(&part[lrow_hi * 4 + head_loc * 2 + 1], v_hi);
        }
    }
    __syncthreads();

    if (t < 128) {
        const int grow = m0 + t;
        if (grow < M) {
            const int hbase = colBase >> 6;        // 0 or 2
            g_asrc[grow * 4 + hbase + 0] = part[t * 4 + 0];
            g_adst[grow * 4 + hbase + 0] = part[t * 4 + 1];
            g_asrc[grow * 4 + hbase + 1] = part[t * 4 + 2];
            g_adst[grow * 4 + hbase + 1] = part[t * 4 + 3];
        }
    }
}

// ---------------- histogram of destinations ----------------------------------
__global__ void hist_kernel(const void* __restrict__ ei, int E) {
    int i = blockIdx.x * blockDim.x + threadIdx.x;
    if (i >= E) return;
    int is64 = g_idx64;
    int d = (int)load_idx(ei, E + i, is64);
    atomicAdd(&g_cnt[d], 1);
}

// ---------------- exclusive scan (single block) -------------------------------
__global__ __launch_bounds__(1024) void scan_kernel(int N) {
    __shared__ int part[1024];
    const int t = threadIdx.x;
    const int C = (N + 1023) / 1024;
    const int begin = t * C;
    const int endi  = min(begin + C, N);

    int sum = 0;
    for (int i = begin; i < endi; i++) sum += g_cnt[i];
    part[t] = sum;
    __syncthreads();
    for (int off = 1; off < 1024; off <<= 1) {
        int v = (t >= off) ? part[t - off] : 0;
        __syncthreads();
        part[t] += v;
        __syncthreads();
    }
    int run = (t == 0) ? 0 : part[t - 1];
    for (int i = begin; i < endi; i++) {
        g_rowptr[i] = run;
        g_cursor[i] = run;
        run += g_cnt[i];
    }
    if (t == 1023) g_rowptr[N] = part[1023];
}

// ---------------- fill CSR slots ----------------------------------------------
__global__ void fill_kernel(const void* __restrict__ ei, int E, int EP) {
    int i = blockIdx.x * blockDim.x + threadIdx.x;
    if (i >= EP) return;
    int is64 = g_idx64;
    int s, d;
    if (i < E) { s = (int)load_idx(ei, i, is64); d = (int)load_idx(ei, E + i, is64); }
    else       { s = d = i - E; }
    int pos = atomicAdd(&g_cursor[d], 1);
    g_srcidx[pos] = s;
}

// ---------------- aggregate: one warp per destination node --------------------
__global__ __launch_bounds__(256) void aggregate_kernel(const float* __restrict__ bias,
                                                        float* __restrict__ out, int N) {
    const int warp = (blockIdx.x * blockDim.x + threadIdx.x) >> 5;
    const int lane = threadIdx.x & 31;
    if (warp >= N) return;

    const int start = g_rowptr[warp];
    const int end   = g_rowptr[warp + 1];

    const float4* asrc4 = reinterpret_cast<const float4*>(g_asrc);
    float4 ad = reinterpret_cast<const float4*>(g_adst)[warp];

    float4 den = make_float4(0.f, 0.f, 0.f, 0.f);
    for (int pos = start + lane; pos < end; pos += 32) {
        int s = g_srcidx[pos];
        float4 a = asrc4[s];
        a.x += ad.x; a.y += ad.y; a.z += ad.z; a.w += ad.w;
        a.x = a.x > 0.f ? a.x : 0.2f * a.x;
        a.y = a.y > 0.f ? a.y : 0.2f * a.y;
        a.z = a.z > 0.f ? a.z : 0.2f * a.z;
        a.w = a.w > 0.f ? a.w : 0.2f * a.w;
        float4 ex = make_float4(expf(a.x), expf(a.y), expf(a.z), expf(a.w));
        reinterpret_cast<float4*>(g_ex)[pos] = ex;
        den.x += ex.x; den.y += ex.y; den.z += ex.z; den.w += ex.w;
    }
#pragma unroll
    for (int off = 16; off; off >>= 1) {
        den.x += __shfl_xor_sync(0xffffffffu, den.x, off);
        den.y += __shfl_xor_sync(0xffffffffu, den.y, off);
        den.z += __shfl_xor_sync(0xffffffffu, den.z, off);
        den.w += __shfl_xor_sync(0xffffffffu, den.w, off);
    }
    float4 inv = make_float4(1.f / den.x, 1.f / den.y, 1.f / den.z, 1.f / den.w);
    float invA = (lane >> 4) ? inv.y : inv.x;
    float invB = (lane >> 4) ? inv.w : inv.z;

    float4 accA = make_float4(0.f, 0.f, 0.f, 0.f);
    float4 accB = make_float4(0.f, 0.f, 0.f, 0.f);

    for (int pos = start; pos < end; pos++) {
        int s = g_srcidx[pos];
        float4 ex = reinterpret_cast<const float4*>(g_ex)[pos];
        float cA = ((lane >> 4) ? ex.y : ex.x) * invA;
        float cB = ((lane >> 4) ? ex.w : ex.z) * invB;
        const float4* xrow = reinterpret_cast<const float4*>(g_xp + (size_t)s * 256);
        float4 vA = xrow[lane];
        float4 vB = xrow[lane + 32];
        accA.x = fmaf(vA.x, cA, accA.x); accA.y = fmaf(vA.y, cA, accA.y);
        accA.z = fmaf(vA.z, cA, accA.z); accA.w = fmaf(vA.w, cA, accA.w);
        accB.x = fmaf(vB.x, cB, accB.x); accB.y = fmaf(vB.y, cB, accB.y);
        accB.z = fmaf(vB.z, cB, accB.z); accB.w = fmaf(vB.w, cB, accB.w);
    }

    float4 bA = reinterpret_cast<const float4*>(bias)[lane];
    float4 bB = reinterpret_cast<const float4*>(bias)[lane + 32];
    accA.x += bA.x; accA.y += bA.y; accA.z += bA.z; accA.w += bA.w;
    accB.x += bB.x; accB.y += bB.y; accB.z += bB.z; accB.w += bB.w;

    float4* orow = reinterpret_cast<float4*>(out + (size_t)warp * 256);
    orow[lane]      = accA;
    orow[lane + 32] = accB;
}

// ---------------- launch -------------------------------------------------------
extern "C" void kernel_launch(void* const* d_in, const int* in_sizes, int n_in,
                              void* d_out, int out_size) {
    const float* x       = (const float*)d_in[0];
    const float* W       = (const float*)d_in[1];
    const float* att_src = (const float*)d_in[2];
    const float* att_dst = (const float*)d_in[3];
    const float* bias    = (const float*)d_in[4];
    const void*  ei      = d_in[5];
    float*       out     = (float*)d_out;

    const int N  = in_sizes[0] / 128;
    const int E  = in_sizes[5] / 2;
    const int EP = E + N;

    detect_init_kernel<<<(N + 255) / 256, 256>>>((const unsigned int*)ei, E, N);

    cudaFuncSetAttribute(gemm_mma_kernel, cudaFuncAttributeMaxDynamicSharedMemorySize,
                         SM_FLOATS * 4);
    dim3 ggrid((N + 127) / 128, 2);
    gemm_mma_kernel<<<ggrid, 256, SM_FLOATS * 4>>>(x, W, att_src, att_dst, N);

    hist_kernel<<<(E + 255) / 256, 256>>>(ei, E);
    scan_kernel<<<1, 1024>>>(N);
    fill_kernel<<<(EP + 255) / 256, 256>>>(ei, E, EP);

    aggregate_kernel<<<(N * 32 + 255) / 256, 256>>>(bias, out, N);
}

// round 6
// speedup vs baseline: 1.9498x; 1.3835x over previous
#include <cuda_runtime.h>
#include <math.h>
#include <stdint.h>

#define NMAX 50000
#define EMAX 800000
#define EPMAX (EMAX + NMAX)
#define SCAN_B 512
#define NBLK ((NMAX + SCAN_B - 1) / SCAN_B)   // 98

// ---------------- scratch (device globals) ----------------------------------
__device__ float g_xp[(size_t)NMAX * 256];   // x @ W  [N, 256]
__device__ float g_asrc[NMAX * 4];           // per-node src logits [N,H]
__device__ float g_adst[NMAX * 4];           // per-node dst logits [N,H]
__device__ int   g_cnt[NMAX];                // in-degree (incl self loop)
__device__ int   g_scan[NMAX];               // block-local inclusive scans
__device__ int   g_bsum[NBLK];               // per-block totals
__device__ int   g_boff[NBLK];               // exclusive block offsets
__device__ int   g_rowptr[NMAX + 1];         // CSR row pointers
__device__ int   g_cursor[NMAX];             // fill cursors
__device__ int   g_srcidx[EPMAX];            // CSR: src node per slot
__device__ float g_ex[(size_t)EPMAX * 4];    // exp(alpha) per slot [.,H]
__device__ int   g_idx64;                    // 1 if edge_index is int64

__device__ __forceinline__ long long load_idx(const void* ei, long long i, int is64) {
    if (is64) return ((const long long*)ei)[i];
    return (long long)((const int*)ei)[i];
}

__device__ __forceinline__ float to_tf32(float f) {
    uint32_t u;
    asm("cvt.rn.tf32.f32 %0, %1;" : "=r"(u) : "f"(f));
    return __uint_as_float(u);
}

// ---------------- detect + init (fused) --------------------------------------
__global__ void detect_init_kernel(const unsigned int* __restrict__ ei32, int E, int N) {
    int i = blockIdx.x * blockDim.x + threadIdx.x;
    if (i < N) g_cnt[i] = 1;
    if (blockIdx.x == 0) {
        unsigned int v = 0;
        if (threadIdx.x < 128 && threadIdx.x < E) v = ei32[2 * threadIdx.x + 1];
        unsigned int any = __ballot_sync(0xffffffffu, v != 0u);
        any = __shfl_sync(0xffffffffu, any, 0);
        __shared__ int flag;
        if (threadIdx.x == 0) flag = 0;
        __syncthreads();
        if ((threadIdx.x & 31) == 0 && any) atomicOr(&flag, 1);
        __syncthreads();
        if (threadIdx.x == 0) g_idx64 = (flag == 0) ? 1 : 0;
    }
}

// ---------------- tf32 mma.sync GEMM + fused attention dots ------------------
#define SM_AS   0
#define SM_BS   16896
#define SM_ATTS 33792
#define SM_ATTD 34048
#define SM_PART 34304
#define SM_FLOATS (34304 + 512)

__global__ __launch_bounds__(256) void gemm_mma_kernel(const float* __restrict__ x,
                                                       const float* __restrict__ W,
                                                       const float* __restrict__ att_src,
                                                       const float* __restrict__ att_dst,
                                                       int M) {
    extern __shared__ float sm[];
    float* As   = sm + SM_AS;
    float* Bs   = sm + SM_BS;
    float* atts = sm + SM_ATTS;
    float* attd = sm + SM_ATTD;
    float* part = sm + SM_PART;

    const int t = threadIdx.x;
    const int m0 = blockIdx.x * 128;
    const int colBase = blockIdx.y * 128;

    if (t < 128) {
        part[t * 4 + 0] = 0.f; part[t * 4 + 1] = 0.f;
        part[t * 4 + 2] = 0.f; part[t * 4 + 3] = 0.f;
    }
    atts[t] = att_src[t];
    attd[t] = att_dst[t];

    for (int i = t; i < 128 * 32; i += 256) {
        int row = i >> 5, c4 = (i & 31) * 4;
        float4 v = make_float4(0.f, 0.f, 0.f, 0.f);
        if (m0 + row < M)
            v = *reinterpret_cast<const float4*>(&x[(size_t)(m0 + row) * 128 + c4]);
        v.x = to_tf32(v.x); v.y = to_tf32(v.y); v.z = to_tf32(v.z); v.w = to_tf32(v.w);
        *reinterpret_cast<float4*>(&As[row * 132 + c4]) = v;
    }
    for (int i = t; i < 128 * 32; i += 256) {
        int row = i >> 5, c4 = (i & 31) * 4;
        float4 v = *reinterpret_cast<const float4*>(&W[(size_t)row * 256 + colBase + c4]);
        v.x = to_tf32(v.x); v.y = to_tf32(v.y); v.z = to_tf32(v.z); v.w = to_tf32(v.w);
        *reinterpret_cast<float4*>(&Bs[row * 132 + c4]) = v;
    }
    __syncthreads();

    const int wid = t >> 5, lane = t & 31;
    const int wr = wid >> 2;
    const int wc = wid & 3;
    const int grp = lane >> 2, t4 = lane & 3;

    float acc[4][4][4];
#pragma unroll
    for (int a = 0; a < 4; a++)
#pragma unroll
        for (int b = 0; b < 4; b++)
#pragma unroll
            for (int c = 0; c < 4; c++) acc[a][b][c] = 0.f;

#pragma unroll
    for (int ks = 0; ks < 16; ks++) {
        const int k0 = ks * 8;
        uint32_t af[4][4];
#pragma unroll
        for (int mf = 0; mf < 4; mf++) {
            const int r = wr * 64 + mf * 16 + grp;
            af[mf][0] = __float_as_uint(As[r * 132 + k0 + t4]);
            af[mf][1] = __float_as_uint(As[(r + 8) * 132 + k0 + t4]);
            af[mf][2] = __float_as_uint(As[r * 132 + k0 + 4 + t4]);
            af[mf][3] = __float_as_uint(As[(r + 8) * 132 + k0 + 4 + t4]);
        }
        uint32_t bf[4][2];
#pragma unroll
        for (int nf = 0; nf < 4; nf++) {
            const int c = wc * 32 + nf * 8 + grp;
            bf[nf][0] = __float_as_uint(Bs[(k0 + t4) * 132 + c]);
            bf[nf][1] = __float_as_uint(Bs[(k0 + 4 + t4) * 132 + c]);
        }
#pragma unroll
        for (int mf = 0; mf < 4; mf++)
#pragma unroll
            for (int nf = 0; nf < 4; nf++) {
                asm volatile(
                    "mma.sync.aligned.m16n8k8.row.col.f32.tf32.tf32.f32 "
                    "{%0,%1,%2,%3}, {%4,%5,%6,%7}, {%8,%9}, {%0,%1,%2,%3};"
                    : "+f"(acc[mf][nf][0]), "+f"(acc[mf][nf][1]),
                      "+f"(acc[mf][nf][2]), "+f"(acc[mf][nf][3])
                    : "r"(af[mf][0]), "r"(af[mf][1]), "r"(af[mf][2]), "r"(af[mf][3]),
                      "r"(bf[nf][0]), "r"(bf[nf][1]));
            }
    }

    const int head_loc = wc >> 1;
#pragma unroll
    for (int mf = 0; mf < 4; mf++) {
        const int lrow_lo = wr * 64 + mf * 16 + grp;
        const int lrow_hi = lrow_lo + 8;
        const int grow_lo = m0 + lrow_lo;
        const int grow_hi = m0 + lrow_hi;

        float s_lo = 0.f, v_lo = 0.f, s_hi = 0.f, v_hi = 0.f;
#pragma unroll
        for (int nf = 0; nf < 4; nf++) {
            const int col = colBase + wc * 32 + nf * 8 + t4 * 2;
            const float a0 = atts[col], a1 = atts[col + 1];
            const float d0 = attd[col], d1 = attd[col + 1];
            s_lo = fmaf(acc[mf][nf][0], a0, fmaf(acc[mf][nf][1], a1, s_lo));
            v_lo = fmaf(acc[mf][nf][0], d0, fmaf(acc[mf][nf][1], d1, v_lo));
            s_hi = fmaf(acc[mf][nf][2], a0, fmaf(acc[mf][nf][3], a1, s_hi));
            v_hi = fmaf(acc[mf][nf][2], d0, fmaf(acc[mf][nf][3], d1, v_hi));
            if (grow_lo < M)
                *reinterpret_cast<float2*>(&g_xp[(size_t)grow_lo * 256 + col]) =
                    make_float2(acc[mf][nf][0], acc[mf][nf][1]);
            if (grow_hi < M)
                *reinterpret_cast<float2*>(&g_xp[(size_t)grow_hi * 256 + col]) =
                    make_float2(acc[mf][nf][2], acc[mf][nf][3]);
        }
#pragma unroll
        for (int off = 1; off < 4; off <<= 1) {
            s_lo += __shfl_xor_sync(0xffffffffu, s_lo, off);
            v_lo += __shfl_xor_sync(0xffffffffu, v_lo, off);
            s_hi += __shfl_xor_sync(0xffffffffu, s_hi, off);
            v_hi += __shfl_xor_sync(0xffffffffu, v_hi, off);
        }
        if (t4 == 0) {
            atomicAdd(&part[lrow_lo * 4 + head_loc * 2 + 0], s_lo);
            atomicAdd(&part[lrow_lo * 4 + head_loc * 2 + 1], v_lo);
            atomicAdd(&part[lrow_hi * 4 + head_loc * 2 + 0], s_hi);
            atomicAdd(&part[lrow_hi * 4 + head_loc * 2 + 1], v_hi);
        }
    }
    __syncthreads();

    if (t < 128) {
        const int grow = m0 + t;
        if (grow < M) {
            const int hbase = colBase >> 6;
            g_asrc[grow * 4 + hbase + 0] = part[t * 4 + 0];
            g_adst[grow * 4 + hbase + 0] = part[t * 4 + 1];
            g_asrc[grow * 4 + hbase + 1] = part[t * 4 + 2];
            g_adst[grow * 4 + hbase + 1] = part[t * 4 + 3];
        }
    }
}

// ---------------- histogram of destinations ----------------------------------
__global__ void hist_kernel(const void* __restrict__ ei, int E) {
    int i = blockIdx.x * blockDim.x + threadIdx.x;
    if (i >= E) return;
    int is64 = g_idx64;
    int d = (int)load_idx(ei, E + i, is64);
    atomicAdd(&g_cnt[d], 1);
}

// ---------------- 3-phase grid-wide scan --------------------------------------
__global__ __launch_bounds__(SCAN_B) void scan1_kernel(int N) {
    __shared__ int s[SCAN_B];
    const int t = threadIdx.x;
    const int i = blockIdx.x * SCAN_B + t;
    int v = (i < N) ? g_cnt[i] : 0;
    s[t] = v;
    __syncthreads();
#pragma unroll
    for (int off = 1; off < SCAN_B; off <<= 1) {
        int u = (t >= off) ? s[t - off] : 0;
        __syncthreads();
        s[t] += u;
        __syncthreads();
    }
    if (i < N) g_scan[i] = s[t];
    if (t == SCAN_B - 1) g_bsum[blockIdx.x] = s[t];
}

__global__ __launch_bounds__(128) void scan2_kernel(int nb) {
    __shared__ int s[128];
    const int t = threadIdx.x;
    s[t] = (t < nb) ? g_bsum[t] : 0;
    __syncthreads();
#pragma unroll
    for (int off = 1; off < 128; off <<= 1) {
        int u = (t >= off) ? s[t - off] : 0;
        __syncthreads();
        s[t] += u;
        __syncthreads();
    }
    if (t < nb) g_boff[t] = (t == 0) ? 0 : s[t - 1];
}

__global__ __launch_bounds__(256) void scan3_kernel(int N) {
    const int i = blockIdx.x * blockDim.x + threadIdx.x;
    if (i >= N) return;
    const int base = g_boff[i / SCAN_B];
    const int incl = base + g_scan[i];
    const int excl = incl - g_cnt[i];
    g_rowptr[i] = excl;
    g_cursor[i] = excl;
    if (i == N - 1) g_rowptr[N] = incl;
}

// ---------------- fill CSR slots ----------------------------------------------
__global__ void fill_kernel(const void* __restrict__ ei, int E, int EP) {
    int i = blockIdx.x * blockDim.x + threadIdx.x;
    if (i >= EP) return;
    int is64 = g_idx64;
    int s, d;
    if (i < E) { s = (int)load_idx(ei, i, is64); d = (int)load_idx(ei, E + i, is64); }
    else       { s = d = i - E; }
    int pos = atomicAdd(&g_cursor[d], 1);
    g_srcidx[pos] = s;
}

// ---------------- aggregate: one warp per destination node --------------------
__global__ __launch_bounds__(256) void aggregate_kernel(const float* __restrict__ bias,
                                                        float* __restrict__ out, int N) {
    const int warp = (blockIdx.x * blockDim.x + threadIdx.x) >> 5;
    const int lane = threadIdx.x & 31;
    if (warp >= N) return;

    const int start = g_rowptr[warp];
    const int end   = g_rowptr[warp + 1];

    const float4* asrc4 = reinterpret_cast<const float4*>(g_asrc);
    float4 ad = reinterpret_cast<const float4*>(g_adst)[warp];

    float4 den = make_float4(0.f, 0.f, 0.f, 0.f);
    for (int pos = start + lane; pos < end; pos += 32) {
        int s = g_srcidx[pos];
        float4 a = asrc4[s];
        a.x += ad.x; a.y += ad.y; a.z += ad.z; a.w += ad.w;
        a.x = a.x > 0.f ? a.x : 0.2f * a.x;
        a.y = a.y > 0.f ? a.y : 0.2f * a.y;
        a.z = a.z > 0.f ? a.z : 0.2f * a.z;
        a.w = a.w > 0.f ? a.w : 0.2f * a.w;
        float4 ex = make_float4(expf(a.x), expf(a.y), expf(a.z), expf(a.w));
        reinterpret_cast<float4*>(g_ex)[pos] = ex;
        den.x += ex.x; den.y += ex.y; den.z += ex.z; den.w += ex.w;
    }
#pragma unroll
    for (int off = 16; off; off >>= 1) {
        den.x += __shfl_xor_sync(0xffffffffu, den.x, off);
        den.y += __shfl_xor_sync(0xffffffffu, den.y, off);
        den.z += __shfl_xor_sync(0xffffffffu, den.z, off);
        den.w += __shfl_xor_sync(0xffffffffu, den.w, off);
    }
    float4 inv = make_float4(1.f / den.x, 1.f / den.y, 1.f / den.z, 1.f / den.w);
    float invA = (lane >> 4) ? inv.y : inv.x;
    float invB = (lane >> 4) ? inv.w : inv.z;

    float4 accA = make_float4(0.f, 0.f, 0.f, 0.f);
    float4 accB = make_float4(0.f, 0.f, 0.f, 0.f);

    for (int pos = start; pos < end; pos++) {
        int s = g_srcidx[pos];
        float4 ex = reinterpret_cast<const float4*>(g_ex)[pos];
        float cA = ((lane >> 4) ? ex.y : ex.x) * invA;
        float cB = ((lane >> 4) ? ex.w : ex.z) * invB;
        const float4* xrow = reinterpret_cast<const float4*>(g_xp + (size_t)s * 256);
        float4 vA = xrow[lane];
        float4 vB = xrow[lane + 32];
        accA.x = fmaf(vA.x, cA, accA.x); accA.y = fmaf(vA.y, cA, accA.y);
        accA.z = fmaf(vA.z, cA, accA.z); accA.w = fmaf(vA.w, cA, accA.w);
        accB.x = fmaf(vB.x, cB, accB.x); accB.y = fmaf(vB.y, cB, accB.y);
        accB.z = fmaf(vB.z, cB, accB.z); accB.w = fmaf(vB.w, cB, accB.w);
    }

    float4 bA = reinterpret_cast<const float4*>(bias)[lane];
    float4 bB = reinterpret_cast<const float4*>(bias)[lane + 32];
    accA.x += bA.x; accA.y += bA.y; accA.z += bA.z; accA.w += bA.w;
    accB.x += bB.x; accB.y += bB.y; accB.z += bB.z; accB.w += bB.w;

    float4* orow = reinterpret_cast<float4*>(out + (size_t)warp * 256);
    orow[lane]      = accA;
    orow[lane + 32] = accB;
}

// ---------------- launch -------------------------------------------------------
extern "C" void kernel_launch(void* const* d_in, const int* in_sizes, int n_in,
                              void* d_out, int out_size) {
    const float* x       = (const float*)d_in[0];
    const float* W       = (const float*)d_in[1];
    const float* att_src = (const float*)d_in[2];
    const float* att_dst = (const float*)d_in[3];
    const float* bias    = (const float*)d_in[4];
    const void*  ei      = d_in[5];
    float*       out     = (float*)d_out;

    const int N  = in_sizes[0] / 128;
    const int E  = in_sizes[5] / 2;
    const int EP = E + N;
    const int nb = (N + SCAN_B - 1) / SCAN_B;

    detect_init_kernel<<<(N + 255) / 256, 256>>>((const unsigned int*)ei, E, N);

    cudaFuncSetAttribute(gemm_mma_kernel, cudaFuncAttributeMaxDynamicSharedMemorySize,
                         SM_FLOATS * 4);
    dim3 ggrid((N + 127) / 128, 2);
    gemm_mma_kernel<<<ggrid, 256, SM_FLOATS * 4>>>(x, W, att_src, att_dst, N);

    hist_kernel<<<(E + 255) / 256, 256>>>(ei, E);
    scan1_kernel<<<nb, SCAN_B>>>(N);
    scan2_kernel<<<1, 128>>>(nb);
    scan3_kernel<<<(N + 255) / 256, 256>>>(N);
    fill_kernel<<<(EP + 255) / 256, 256>>>(ei, E, EP);

    aggregate_kernel<<<(N * 32 + 255) / 256, 256>>>(bias, out, N);
}

// round 7
// speedup vs baseline: 2.0529x; 1.0529x over previous
#include <cuda_runtime.h>
#include <cuda_fp16.h>
#include <math.h>
#include <stdint.h>

#define NMAX 50000
#define EMAX 800000
#define EPMAX (EMAX + NMAX)
#define SCAN_B 512
#define NBLK ((NMAX + SCAN_B - 1) / SCAN_B)   // 98

// ---------------- scratch (device globals) ----------------------------------
__device__ __half2 g_xph[(size_t)NMAX * 128]; // x @ W in fp16  [N, 256]
__device__ float g_asrc[NMAX * 4];            // per-node src logits [N,H]
__device__ float g_adst[NMAX * 4];            // per-node dst logits [N,H]
__device__ int   g_cnt[NMAX];                 // in-degree (incl self loop)
__device__ int   g_scan[NMAX];                // block-local inclusive scans
__device__ int   g_bsum[NBLK];                // per-block totals
__device__ int   g_boff[NBLK];                // exclusive block offsets
__device__ int   g_rowptr[NMAX + 1];          // CSR row pointers
__device__ int   g_cursor[NMAX];              // fill cursors
__device__ int   g_srcidx[EPMAX];             // CSR: src node per slot
__device__ float g_ex[(size_t)EPMAX * 4];     // exp(alpha) per slot [.,H]
__device__ int   g_idx64;                     // 1 if edge_index is int64

__device__ __forceinline__ long long load_idx(const void* ei, long long i, int is64) {
    if (is64) return ((const long long*)ei)[i];
    return (long long)((const int*)ei)[i];
}

__device__ __forceinline__ float to_tf32(float f) {
    uint32_t u;
    asm("cvt.rn.tf32.f32 %0, %1;" : "=r"(u) : "f"(f));
    return __uint_as_float(u);
}

// ---------------- detect + init (fused) --------------------------------------
__global__ void detect_init_kernel(const unsigned int* __restrict__ ei32, int E, int N) {
    int i = blockIdx.x * blockDim.x + threadIdx.x;
    if (i < N) g_cnt[i] = 1;
    if (blockIdx.x == 0) {
        unsigned int v = 0;
        if (threadIdx.x < 128 && threadIdx.x < E) v = ei32[2 * threadIdx.x + 1];
        unsigned int any = __ballot_sync(0xffffffffu, v != 0u);
        any = __shfl_sync(0xffffffffu, any, 0);
        __shared__ int flag;
        if (threadIdx.x == 0) flag = 0;
        __syncthreads();
        if ((threadIdx.x & 31) == 0 && any) atomicOr(&flag, 1);
        __syncthreads();
        if (threadIdx.x == 0) g_idx64 = (flag == 0) ? 1 : 0;
    }
}

// ---------------- tf32 mma.sync GEMM + fused attention dots ------------------
#define SM_AS   0
#define SM_BS   16896
#define SM_ATTS 33792
#define SM_ATTD 34048
#define SM_PART 34304
#define SM_FLOATS (34304 + 512)

__global__ __launch_bounds__(256) void gemm_mma_kernel(const float* __restrict__ x,
                                                       const float* __restrict__ W,
                                                       const float* __restrict__ att_src,
                                                       const float* __restrict__ att_dst,
                                                       int M) {
    extern __shared__ float sm[];
    float* As   = sm + SM_AS;
    float* Bs   = sm + SM_BS;
    float* atts = sm + SM_ATTS;
    float* attd = sm + SM_ATTD;
    float* part = sm + SM_PART;

    const int t = threadIdx.x;
    const int m0 = blockIdx.x * 128;
    const int colBase = blockIdx.y * 128;

    if (t < 128) {
        part[t * 4 + 0] = 0.f; part[t * 4 + 1] = 0.f;
        part[t * 4 + 2] = 0.f; part[t * 4 + 3] = 0.f;
    }
    atts[t] = att_src[t];
    attd[t] = att_dst[t];

    for (int i = t; i < 128 * 32; i += 256) {
        int row = i >> 5, c4 = (i & 31) * 4;
        float4 v = make_float4(0.f, 0.f, 0.f, 0.f);
        if (m0 + row < M)
            v = *reinterpret_cast<const float4*>(&x[(size_t)(m0 + row) * 128 + c4]);
        v.x = to_tf32(v.x); v.y = to_tf32(v.y); v.z = to_tf32(v.z); v.w = to_tf32(v.w);
        *reinterpret_cast<float4*>(&As[row * 132 + c4]) = v;
    }
    for (int i = t; i < 128 * 32; i += 256) {
        int row = i >> 5, c4 = (i & 31) * 4;
        float4 v = *reinterpret_cast<const float4*>(&W[(size_t)row * 256 + colBase + c4]);
        v.x = to_tf32(v.x); v.y = to_tf32(v.y); v.z = to_tf32(v.z); v.w = to_tf32(v.w);
        *reinterpret_cast<float4*>(&Bs[row * 132 + c4]) = v;
    }
    __syncthreads();

    const int wid = t >> 5, lane = t & 31;
    const int wr = wid >> 2;
    const int wc = wid & 3;
    const int grp = lane >> 2, t4 = lane & 3;

    float acc[4][4][4];
#pragma unroll
    for (int a = 0; a < 4; a++)
#pragma unroll
        for (int b = 0; b < 4; b++)
#pragma unroll
            for (int c = 0; c < 4; c++) acc[a][b][c] = 0.f;

#pragma unroll
    for (int ks = 0; ks < 16; ks++) {
        const int k0 = ks * 8;
        uint32_t af[4][4];
#pragma unroll
        for (int mf = 0; mf < 4; mf++) {
            const int r = wr * 64 + mf * 16 + grp;
            af[mf][0] = __float_as_uint(As[r * 132 + k0 + t4]);
            af[mf][1] = __float_as_uint(As[(r + 8) * 132 + k0 + t4]);
            af[mf][2] = __float_as_uint(As[r * 132 + k0 + 4 + t4]);
            af[mf][3] = __float_as_uint(As[(r + 8) * 132 + k0 + 4 + t4]);
        }
        uint32_t bf[4][2];
#pragma unroll
        for (int nf = 0; nf < 4; nf++) {
            const int c = wc * 32 + nf * 8 + grp;
            bf[nf][0] = __float_as_uint(Bs[(k0 + t4) * 132 + c]);
            bf[nf][1] = __float_as_uint(Bs[(k0 + 4 + t4) * 132 + c]);
        }
#pragma unroll
        for (int mf = 0; mf < 4; mf++)
#pragma unroll
            for (int nf = 0; nf < 4; nf++) {
                asm volatile(
                    "mma.sync.aligned.m16n8k8.row.col.f32.tf32.tf32.f32 "
                    "{%0,%1,%2,%3}, {%4,%5,%6,%7}, {%8,%9}, {%0,%1,%2,%3};"
                    : "+f"(acc[mf][nf][0]), "+f"(acc[mf][nf][1]),
                      "+f"(acc[mf][nf][2]), "+f"(acc[mf][nf][3])
                    : "r"(af[mf][0]), "r"(af[mf][1]), "r"(af[mf][2]), "r"(af[mf][3]),
                      "r"(bf[nf][0]), "r"(bf[nf][1]));
            }
    }

    const int head_loc = wc >> 1;
#pragma unroll
    for (int mf = 0; mf < 4; mf++) {
        const int lrow_lo = wr * 64 + mf * 16 + grp;
        const int lrow_hi = lrow_lo + 8;
        const int grow_lo = m0 + lrow_lo;
        const int grow_hi = m0 + lrow_hi;

        float s_lo = 0.f, v_lo = 0.f, s_hi = 0.f, v_hi = 0.f;
#pragma unroll
        for (int nf = 0; nf < 4; nf++) {
            const int col = colBase + wc * 32 + nf * 8 + t4 * 2;
            const float a0 = atts[col], a1 = atts[col + 1];
            const float d0 = attd[col], d1 = attd[col + 1];
            s_lo = fmaf(acc[mf][nf][0], a0, fmaf(acc[mf][nf][1], a1, s_lo));
            v_lo = fmaf(acc[mf][nf][0], d0, fmaf(acc[mf][nf][1], d1, v_lo));
            s_hi = fmaf(acc[mf][nf][2], a0, fmaf(acc[mf][nf][3], a1, s_hi));
            v_hi = fmaf(acc[mf][nf][2], d0, fmaf(acc[mf][nf][3], d1, v_hi));
            if (grow_lo < M)
                g_xph[(size_t)grow_lo * 128 + (col >> 1)] =
                    __floats2half2_rn(acc[mf][nf][0], acc[mf][nf][1]);
            if (grow_hi < M)
                g_xph[(size_t)grow_hi * 128 + (col >> 1)] =
                    __floats2half2_rn(acc[mf][nf][2], acc[mf][nf][3]);
        }
#pragma unroll
        for (int off = 1; off < 4; off <<= 1) {
            s_lo += __shfl_xor_sync(0xffffffffu, s_lo, off);
            v_lo += __shfl_xor_sync(0xffffffffu, v_lo, off);
            s_hi += __shfl_xor_sync(0xffffffffu, s_hi, off);
            v_hi += __shfl_xor_sync(0xffffffffu, v_hi, off);
        }
        if (t4 == 0) {
            atomicAdd(&part[lrow_lo * 4 + head_loc * 2 + 0], s_lo);
            atomicAdd(&part[lrow_lo * 4 + head_loc * 2 + 1], v_lo);
            atomicAdd(&part[lrow_hi * 4 + head_loc * 2 + 0], s_hi);
            atomicAdd(&part[lrow_hi * 4 + head_loc * 2 + 1], v_hi);
        }
    }
    __syncthreads();

    if (t < 128) {
        const int grow = m0 + t;
        if (grow < M) {
            const int hbase = colBase >> 6;
            g_asrc[grow * 4 + hbase + 0] = part[t * 4 + 0];
            g_adst[grow * 4 + hbase + 0] = part[t * 4 + 1];
            g_asrc[grow * 4 + hbase + 1] = part[t * 4 + 2];
            g_adst[grow * 4 + hbase + 1] = part[t * 4 + 3];
        }
    }
}

// ---------------- histogram of destinations ----------------------------------
__global__ void hist_kernel(const void* __restrict__ ei, int E) {
    int i = blockIdx.x * blockDim.x + threadIdx.x;
    if (i >= E) return;
    int is64 = g_idx64;
    int d = (int)load_idx(ei, E + i, is64);
    atomicAdd(&g_cnt[d], 1);
}

// ---------------- 3-phase grid-wide scan --------------------------------------
__global__ __launch_bounds__(SCAN_B) void scan1_kernel(int N) {
    __shared__ int s[SCAN_B];
    const int t = threadIdx.x;
    const int i = blockIdx.x * SCAN_B + t;
    int v = (i < N) ? g_cnt[i] : 0;
    s[t] = v;
    __syncthreads();
#pragma unroll
    for (int off = 1; off < SCAN_B; off <<= 1) {
        int u = (t >= off) ? s[t - off] : 0;
        __syncthreads();
        s[t] += u;
        __syncthreads();
    }
    if (i < N) g_scan[i] = s[t];
    if (t == SCAN_B - 1) g_bsum[blockIdx.x] = s[t];
}

__global__ __launch_bounds__(128) void scan2_kernel(int nb) {
    __shared__ int s[128];
    const int t = threadIdx.x;
    s[t] = (t < nb) ? g_bsum[t] : 0;
    __syncthreads();
#pragma unroll
    for (int off = 1; off < 128; off <<= 1) {
        int u = (t >= off) ? s[t - off] : 0;
        __syncthreads();
        s[t] += u;
        __syncthreads();
    }
    if (t < nb) g_boff[t] = (t == 0) ? 0 : s[t - 1];
}

__global__ __launch_bounds__(256) void scan3_kernel(int N) {
    const int i = blockIdx.x * blockDim.x + threadIdx.x;
    if (i >= N) return;
    const int base = g_boff[i / SCAN_B];
    const int incl = base + g_scan[i];
    const int excl = incl - g_cnt[i];
    g_rowptr[i] = excl;
    g_cursor[i] = excl;
    if (i == N - 1) g_rowptr[N] = incl;
}

// ---------------- fill CSR slots ----------------------------------------------
__global__ void fill_kernel(const void* __restrict__ ei, int E, int EP) {
    int i = blockIdx.x * blockDim.x + threadIdx.x;
    if (i >= EP) return;
    int is64 = g_idx64;
    int s, d;
    if (i < E) { s = (int)load_idx(ei, i, is64); d = (int)load_idx(ei, E + i, is64); }
    else       { s = d = i - E; }
    int pos = atomicAdd(&g_cursor[d], 1);
    g_srcidx[pos] = s;
}

// ---------------- aggregate: one warp per destination node --------------------
// fp16 xp rows: 512 B/row = 32 lanes x uint4. Lane owns channels [lane*8, +8),
// all within head (lane>>3).
__global__ __launch_bounds__(256) void aggregate_kernel(const float* __restrict__ bias,
                                                        float* __restrict__ out, int N) {
    const int warp = (blockIdx.x * blockDim.x + threadIdx.x) >> 5;
    const int lane = threadIdx.x & 31;
    if (warp >= N) return;

    const int start = g_rowptr[warp];
    const int end   = g_rowptr[warp + 1];

    const float4* asrc4 = reinterpret_cast<const float4*>(g_asrc);
    float4 ad = reinterpret_cast<const float4*>(g_adst)[warp];

    float4 den = make_float4(0.f, 0.f, 0.f, 0.f);
    for (int pos = start + lane; pos < end; pos += 32) {
        int s = g_srcidx[pos];
        float4 a = asrc4[s];
        a.x += ad.x; a.y += ad.y; a.z += ad.z; a.w += ad.w;
        a.x = a.x > 0.f ? a.x : 0.2f * a.x;
        a.y = a.y > 0.f ? a.y : 0.2f * a.y;
        a.z = a.z > 0.f ? a.z : 0.2f * a.z;
        a.w = a.w > 0.f ? a.w : 0.2f * a.w;
        float4 ex = make_float4(expf(a.x), expf(a.y), expf(a.z), expf(a.w));
        reinterpret_cast<float4*>(g_ex)[pos] = ex;
        den.x += ex.x; den.y += ex.y; den.z += ex.z; den.w += ex.w;
    }
#pragma unroll
    for (int off = 16; off; off >>= 1) {
        den.x += __shfl_xor_sync(0xffffffffu, den.x, off);
        den.y += __shfl_xor_sync(0xffffffffu, den.y, off);
        den.z += __shfl_xor_sync(0xffffffffu, den.z, off);
        den.w += __shfl_xor_sync(0xffffffffu, den.w, off);
    }

    const int h = lane >> 3;   // head owned by this lane
    float invH;
    {
        float d0 = (h & 2) ? ((h & 1) ? den.w : den.z) : ((h & 1) ? den.y : den.x);
        invH = 1.f / d0;
    }

    float acc[8];
#pragma unroll
    for (int j = 0; j < 8; j++) acc[j] = 0.f;

    const uint4* exu = reinterpret_cast<const uint4*>(g_ex);
    for (int pos = start; pos < end; pos++) {
        int s = g_srcidx[pos];                       // broadcast
        uint4 exr = exu[pos];                        // broadcast (16B)
        float exh = (h & 2) ? ((h & 1) ? __uint_as_float(exr.w) : __uint_as_float(exr.z))
                            : ((h & 1) ? __uint_as_float(exr.y) : __uint_as_float(exr.x));
        float c = exh * invH;
        uint4 v = reinterpret_cast<const uint4*>(g_xph + (size_t)s * 128)[lane];
        float2 f0 = __half22float2(*reinterpret_cast<__half2*>(&v.x));
        float2 f1 = __half22float2(*reinterpret_cast<__half2*>(&v.y));
        float2 f2 = __half22float2(*reinterpret_cast<__half2*>(&v.z));
        float2 f3 = __half22float2(*reinterpret_cast<__half2*>(&v.w));
        acc[0] = fmaf(f0.x, c, acc[0]); acc[1] = fmaf(f0.y, c, acc[1]);
        acc[2] = fmaf(f1.x, c, acc[2]); acc[3] = fmaf(f1.y, c, acc[3]);
        acc[4] = fmaf(f2.x, c, acc[4]); acc[5] = fmaf(f2.y, c, acc[5]);
        acc[6] = fmaf(f3.x, c, acc[6]); acc[7] = fmaf(f3.y, c, acc[7]);
    }

    const float4 b0 = *reinterpret_cast<const float4*>(&bias[lane * 8]);
    const float4 b1 = *reinterpret_cast<const float4*>(&bias[lane * 8 + 4]);
    float* orow = out + (size_t)warp * 256 + lane * 8;
    *reinterpret_cast<float4*>(orow) =
        make_float4(acc[0] + b0.x, acc[1] + b0.y, acc[2] + b0.z, acc[3] + b0.w);
    *reinterpret_cast<float4*>(orow + 4) =
        make_float4(acc[4] + b1.x, acc[5] + b1.y, acc[6] + b1.z, acc[7] + b1.w);
}

// ---------------- launch -------------------------------------------------------
extern "C" void kernel_launch(void* const* d_in, const int* in_sizes, int n_in,
                              void* d_out, int out_size) {
    const float* x       = (const float*)d_in[0];
    const float* W       = (const float*)d_in[1];
    const float* att_src = (const float*)d_in[2];
    const float* att_dst = (const float*)d_in[3];
    const float* bias    = (const float*)d_in[4];
    const void*  ei      = d_in[5];
    float*       out     = (float*)d_out;

    const int N  = in_sizes[0] / 128;
    const int E  = in_sizes[5] / 2;
    const int EP = E + N;
    const int nb = (N + SCAN_B - 1) / SCAN_B;

    detect_init_kernel<<<(N + 255) / 256, 256>>>((const unsigned int*)ei, E, N);

    cudaFuncSetAttribute(gemm_mma_kernel, cudaFuncAttributeMaxDynamicSharedMemorySize,
                         SM_FLOATS * 4);
    dim3 ggrid((N + 127) / 128, 2);
    gemm_mma_kernel<<<ggrid, 256, SM_FLOATS * 4>>>(x, W, att_src, att_dst, N);

    hist_kernel<<<(E + 255) / 256, 256>>>(ei, E);
    scan1_kernel<<<nb, SCAN_B>>>(N);
    scan2_kernel<<<1, 128>>>(nb);
    scan3_kernel<<<(N + 255) / 256, 256>>>(N);
    fill_kernel<<<(EP + 255) / 256, 256>>>(ei, E, EP);

    aggregate_kernel<<<(N * 32 + 255) / 256, 256>>>(bias, out, N);
}